// round 7
// baseline (speedup 1.0000x reference)
#include <cuda_runtime.h>
#include <cuda_fp16.h>
#include <float.h>

// Problem constants
#define BB   64
#define DD   64
#define TTm  4096
#define KKm  512
#define TILE 128
#define NTH  256
#define N_ELEM ((size_t)BB * DD * TTm)
#define WINDOW 8e-4f

// smem byte offsets
#define SM_X2    0         // 128 f
#define SM_C2    512       // 512 f
#define SM_KIDX  2560      // 128 i
#define SM_WRED  3072      // 8 f
#define SM_QCNT  3104      // 1 i
#define SM_QUE   3136      // 128 i
#define SM_ZS    3712      // 128x64 f32 [d][t]            (32768 B)
#define SM_AS    36480     // 128 rows x 144 B fp16        (18432 B)
#define SM_BS    54912     // 128 rows x 144 B fp16        (18432 B)
#define SM_TOTAL 73344

#define ASTR 144
#define BSTR 144

__device__ double g_loss;
__device__ float  g_c2[KKm];
__device__ __half g_eh[KKm * DD];

__device__ __forceinline__ unsigned s2u(const void* p) {
    unsigned a;
    asm("{ .reg .u64 t; cvta.to.shared.u64 t, %1; cvt.u32.u64 %0, t; }"
        : "=r"(a) : "l"(p));
    return a;
}
__device__ __forceinline__ void ldm_x4(unsigned* r, unsigned addr) {
    asm volatile("ldmatrix.sync.aligned.m8n8.x4.shared.b16 {%0,%1,%2,%3}, [%4];"
        : "=r"(r[0]), "=r"(r[1]), "=r"(r[2]), "=r"(r[3]) : "r"(addr));
}
__device__ __forceinline__ void mma16816(float* c, const unsigned* a,
                                         unsigned b0, unsigned b1) {
    asm volatile(
        "mma.sync.aligned.m16n8k16.row.col.f32.f16.f16.f32 "
        "{%0,%1,%2,%3}, {%4,%5,%6,%7}, {%8,%9}, {%0,%1,%2,%3};"
        : "+f"(c[0]), "+f"(c[1]), "+f"(c[2]), "+f"(c[3])
        : "r"(a[0]), "r"(a[1]), "r"(a[2]), "r"(a[3]), "r"(b0), "r"(b1));
}

// ---------------------------------------------------------------------------
// prep: c2 (rounded squares + pairwise tree, matches reference) + fp16 emb
// ---------------------------------------------------------------------------
__global__ void vq_prep(const float* __restrict__ emb) {
    int k = blockIdx.x * 128 + threadIdx.x;
    if (k == 0) g_loss = 0.0;
    const float* e = emb + k * DD;
    float p[DD];
    #pragma unroll
    for (int d = 0; d < DD; d++) {
        float v = e[d];
        p[d] = __fmul_rn(v, v);
        g_eh[k * DD + d] = __float2half_rn(v);
    }
    #pragma unroll
    for (int w = DD; w > 1; w >>= 1)
        #pragma unroll
        for (int i = 0; i < DD / 2; i++)
            if (i < w / 2) p[i] = __fadd_rn(p[2 * i], p[2 * i + 1]);
    g_c2[k] = p[0];
}

// ---------------------------------------------------------------------------
// main
// ---------------------------------------------------------------------------
__global__ __launch_bounds__(NTH, 2)
void vq_main(const float* __restrict__ z, const float* __restrict__ emb,
             float* __restrict__ out) {
    extern __shared__ char smem[];
    const unsigned sb = s2u(smem);
    const int tid = threadIdx.x;
    const int wid = tid >> 5, lane = tid & 31;
    const int g = lane >> 2, t = lane & 3;
    const int m0 = wid * 16;
    const int tile = blockIdx.x, b = tile >> 5, t0 = (tile & 31) * TILE;
    const size_t zbase = (size_t)b * DD * TTm + t0;

    float* zs   = (float*)(smem + SM_ZS);
    float* x2s  = (float*)(smem + SM_X2);
    float* c2s  = (float*)(smem + SM_C2);
    int*   kidx = (int*)(smem + SM_KIDX);
    float* wred = (float*)(smem + SM_WRED);
    int*   qcnt = (int*)(smem + SM_QCNT);
    int*   que  = (int*)(smem + SM_QUE);

    if (tid == 0) *qcnt = 0;

    // ---- load z tile fp32 [d][t] coalesced; c2 ----
    for (int i = tid; i < DD * TILE / 4; i += NTH) {
        int row = i >> 5, col = (i & 31) << 2;
        *(float4*)(zs + row * TILE + col) =
            *(const float4*)(z + zbase + (size_t)row * TTm + col);
    }
    for (int i = tid; i < KKm; i += NTH) c2s[i] = g_c2[i];
    __syncthreads();

    // ---- A tile: z -> fp16 [tok][d], 144B stride ----
    for (int i = tid; i < TILE * DD / 2; i += NTH) {
        int tok = i >> 5, d = (i & 31) * 2;
        __half2 hp = __floats2half2_rn(zs[d * TILE + tok], zs[(d + 1) * TILE + tok]);
        *(__half2*)(smem + SM_AS + tok * ASTR + d * 2) = hp;
    }
    // ---- per-token ||x||^2 (exact fp32 chain) ----
    if (tid < TILE) {
        float s = 0.f;
        #pragma unroll
        for (int d = 0; d < DD; d++) { float v = zs[d * TILE + tid]; s = fmaf(v, v, s); }
        x2s[tid] = s;
    }

    // running (min, argmin, 2nd-min) for this thread's two fragment rows
    float d1a = FLT_MAX, d2a = FLT_MAX, d1b = FLT_MAX, d2b = FLT_MAX;
    int   k1a = 0, k1b = 0;

    #pragma unroll 1
    for (int bc = 0; bc < 4; bc++) {
        __syncthreads();                 // A ready (bc=0) / prev BS consumed
        for (int i = tid; i < 128 * 8; i += NTH) {
            int code = i >> 3, d8 = (i & 7) << 3;
            *(uint4*)(smem + SM_BS + code * BSTR + d8 * 2) =
                *(const uint4*)(g_eh + (size_t)(bc * 128 + code) * DD + d8);
        }
        __syncthreads();

        #pragma unroll 1
        for (int ns = 0; ns < 4; ns++) {
            float acc[4][4] = {};
            #pragma unroll
            for (int ks = 0; ks < 4; ks++) {
                unsigned a[4], bfr[8];
                unsigned aaddr = sb + SM_AS + (m0 + (lane & 15)) * ASTR
                               + ks * 32 + (lane >> 4) * 16;
                ldm_x4(a, aaddr);
                #pragma unroll
                for (int h = 0; h < 2; h++) {
                    int ntsel = h * 2 + (lane >> 4);
                    unsigned baddr = sb + SM_BS + (ns * 32 + ntsel * 8 + (lane & 7)) * BSTR
                                   + ks * 32 + ((lane >> 3) & 1) * 16;
                    ldm_x4(bfr + h * 4, baddr);
                }
                #pragma unroll
                for (int nt = 0; nt < 4; nt++)
                    mma16816(acc[nt], a, bfr[2 * nt], bfr[2 * nt + 1]);
            }
            // epilogue: s = c2 - 2*dot, update triples in registers
            #pragma unroll
            for (int nt = 0; nt < 4; nt++) {
                int colg = bc * 128 + ns * 32 + nt * 8 + 2 * t;
                float2 c2v = *(const float2*)(c2s + colg);
                float v0 = fmaf(-2.f, acc[nt][0], c2v.x);
                float v1 = fmaf(-2.f, acc[nt][1], c2v.y);
                float v2 = fmaf(-2.f, acc[nt][2], c2v.x);
                float v3 = fmaf(-2.f, acc[nt][3], c2v.y);
                if (v0 < d1a) { d2a = d1a; d1a = v0; k1a = colg; }     else if (v0 < d2a) d2a = v0;
                if (v1 < d1a) { d2a = d1a; d1a = v1; k1a = colg + 1; } else if (v1 < d2a) d2a = v1;
                if (v2 < d1b) { d2b = d1b; d1b = v2; k1b = colg; }     else if (v2 < d2b) d2b = v2;
                if (v3 < d1b) { d2b = d1b; d1b = v3; k1b = colg + 1; } else if (v3 < d2b) d2b = v3;
            }
        }
    }

    // ---- quad reduce (threads t=0..3 share rows m0+g, m0+g+8) ----
    #pragma unroll
    for (int off = 1; off < 4; off <<= 1) {
        float od1 = __shfl_xor_sync(0xffffffffu, d1a, off, 4);
        int   ok1 = __shfl_xor_sync(0xffffffffu, k1a, off, 4);
        float od2 = __shfl_xor_sync(0xffffffffu, d2a, off, 4);
        if (od1 < d1a) { d2a = fminf(d1a, od2); d1a = od1; k1a = ok1; }
        else           { d2a = fminf(d2a, od1); }
        od1 = __shfl_xor_sync(0xffffffffu, d1b, off, 4);
        ok1 = __shfl_xor_sync(0xffffffffu, k1b, off, 4);
        od2 = __shfl_xor_sync(0xffffffffu, d2b, off, 4);
        if (od1 < d1b) { d2b = fminf(d1b, od2); d1b = od1; k1b = ok1; }
        else           { d2b = fminf(d2b, od1); }
    }
    if (t == 0) {
        kidx[m0 + g]     = (d2a - d1a > WINDOW) ? k1a : -1;
        kidx[m0 + g + 8] = (d2b - d1b > WINDOW) ? k1b : -1;
    }
    __syncthreads();

    // ---- queue ambiguous tokens ----
    if (tid < TILE && kidx[tid] < 0) {
        int pos = atomicAdd(qcnt, 1);
        que[pos] = tid;
    }
    __syncthreads();

    // ---- warp-cooperative exact rescue (reference-rounded, lexicographic) ----
    const int qc = *qcnt;
    for (int q = wid; q < qc; q += NTH / 32) {
        int tok = que[q];
        float x2 = x2s[tok];
        float s[16];
        #pragma unroll
        for (int cc = 0; cc < 16; cc++) s[cc] = 0.f;
        #pragma unroll
        for (int chunk = 0; chunk < 4; chunk++) {
            float zv[16];
            #pragma unroll
            for (int dd = 0; dd < 16; dd++) zv[dd] = zs[(chunk * 16 + dd) * TILE + tok];
            #pragma unroll
            for (int cc = 0; cc < 16; cc++) {
                const float* e = emb + (lane * 16 + cc) * DD + chunk * 16;
                #pragma unroll
                for (int dq = 0; dq < 4; dq++) {
                    float4 ev = __ldg((const float4*)(e + dq * 4));
                    s[cc] = fmaf(zv[dq * 4 + 0], ev.x, s[cc]);
                    s[cc] = fmaf(zv[dq * 4 + 1], ev.y, s[cc]);
                    s[cc] = fmaf(zv[dq * 4 + 2], ev.z, s[cc]);
                    s[cc] = fmaf(zv[dq * 4 + 3], ev.w, s[cc]);
                }
            }
        }
        float bd = FLT_MAX; int bk = 0;
        #pragma unroll
        for (int cc = 0; cc < 16; cc++) {
            int code = lane * 16 + cc;
            float dd = __fsub_rn(__fadd_rn(x2, c2s[code]), __fmul_rn(2.f, s[cc]));
            if (dd < bd) { bd = dd; bk = code; }
        }
        #pragma unroll
        for (int off = 16; off > 0; off >>= 1) {
            float od = __shfl_down_sync(0xffffffffu, bd, off);
            int   ok = __shfl_down_sync(0xffffffffu, bk, off);
            if (od < bd || (od == bd && ok < bk)) { bd = od; bk = ok; }
        }
        if (lane == 0) kidx[tok] = bk;
    }
    __syncthreads();

    // ---- gather + straight-through output + loss (reference rounding) ----
    float lsum = 0.f;
    for (int i = tid; i < DD * TILE; i += NTH) {
        int d = i >> 7, tt = i & 127;
        float q  = __ldg(emb + kidx[tt] * DD + d);
        float zv = zs[d * TILE + tt];
        float diff = __fsub_rn(q, zv);
        out[zbase + (size_t)d * TTm + tt] = __fadd_rn(zv, diff);
        lsum = fmaf(diff, diff, lsum);
    }
    #pragma unroll
    for (int o = 16; o > 0; o >>= 1)
        lsum += __shfl_down_sync(0xffffffffu, lsum, o);
    if (lane == 0) wred[wid] = lsum;
    __syncthreads();
    if (tid == 0) {
        float sacc = 0.f;
        #pragma unroll
        for (int w = 0; w < NTH / 32; w++) sacc += wred[w];
        atomicAdd(&g_loss, (double)sacc);
    }
}

// ---------------------------------------------------------------------------
__global__ void vq_fin(float* __restrict__ out) {
    double m = g_loss / (double)N_ELEM;
    out[N_ELEM]     = (float)m;
    out[N_ELEM + 1] = (float)(0.25 * m);
}

// ---------------------------------------------------------------------------
extern "C" void kernel_launch(void* const* d_in, const int* in_sizes, int n_in,
                              void* d_out, int out_size) {
    const float* z   = (const float*)d_in[0];
    const float* emb = (const float*)d_in[1];
    float*       out = (float*)d_out;

    (void)cudaFuncSetAttribute(vq_main,
                               cudaFuncAttributeMaxDynamicSharedMemorySize,
                               SM_TOTAL);

    vq_prep<<<4, 128>>>(emb);
    vq_main<<<(BB * TTm) / TILE, NTH, SM_TOTAL>>>(z, emb, out);
    vq_fin<<<1, 1>>>(out);
}